// round 1
// baseline (speedup 1.0000x reference)
#include <cuda_runtime.h>

#define N_B   4
#define L_SEQ 2048
#define N_H   16
#define D_H   32
#define DIM   512
#define CHUNK 32
#define N_CHUNK (L_SEQ / CHUNK)     // 64
#define TOT_ROWS (N_B * L_SEQ)      // 8192

// Scratch (allocation-free rule: static __device__ arrays)
__device__ float g_Q[TOT_ROWS * DIM];
__device__ float g_K[TOT_ROWS * DIM];
__device__ float g_V[TOT_ROWS * DIM];
__device__ float g_S[N_B * N_H * N_CHUNK * D_H * D_H];   // per-chunk KV sums -> exclusive prefix

// ---------------------------------------------------------------------------
// Kernel 1: projection GEMM out[m,n] = sum_k X[m,k] * W[n,k]
// X: (8192,512) row-major, W: (512,512) row-major (torch Linear: y = x @ W^T)
// blockIdx.z selects {Q (softmax), K (softmax), V (plain)}.
// Tile: 64x64 per block, BK=16, 256 threads, 4x4 micro-tile per thread.
// ---------------------------------------------------------------------------
__global__ __launch_bounds__(256) void proj_kernel(
    const float* __restrict__ query, const float* __restrict__ key,
    const float* __restrict__ Wq, const float* __restrict__ Wk,
    const float* __restrict__ Wv)
{
    const int mat = blockIdx.z;
    const float* __restrict__ X = (mat == 0) ? query : key;
    const float* __restrict__ W = (mat == 0) ? Wq : (mat == 1 ? Wk : Wv);
    float* __restrict__ O = (mat == 0) ? g_Q : (mat == 1 ? g_K : g_V);
    const bool do_sm = (mat < 2);

    __shared__ float As[16][64];   // [k][m]
    __shared__ float Bs[16][64];   // [k][n]
    __shared__ float T[64][65];    // softmax staging

    const int tid = threadIdx.x;
    const int tx = tid & 15;
    const int ty = tid >> 4;
    const int bm = blockIdx.y * 64;
    const int bn = blockIdx.x * 64;

    const int lm = tid >> 2;          // 0..63
    const int lk = (tid & 3) * 4;     // 0,4,8,12

    float acc[4][4] = {};

    for (int bk = 0; bk < DIM; bk += 16) {
        float4 av = *reinterpret_cast<const float4*>(&X[(size_t)(bm + lm) * DIM + bk + lk]);
        As[lk + 0][lm] = av.x; As[lk + 1][lm] = av.y;
        As[lk + 2][lm] = av.z; As[lk + 3][lm] = av.w;
        float4 bv = *reinterpret_cast<const float4*>(&W[(size_t)(bn + lm) * DIM + bk + lk]);
        Bs[lk + 0][lm] = bv.x; Bs[lk + 1][lm] = bv.y;
        Bs[lk + 2][lm] = bv.z; Bs[lk + 3][lm] = bv.w;
        __syncthreads();
        #pragma unroll
        for (int kk = 0; kk < 16; kk++) {
            float4 a4 = *reinterpret_cast<const float4*>(&As[kk][ty * 4]);
            float4 b4 = *reinterpret_cast<const float4*>(&Bs[kk][tx * 4]);
            float a[4] = {a4.x, a4.y, a4.z, a4.w};
            float b[4] = {b4.x, b4.y, b4.z, b4.w};
            #pragma unroll
            for (int i = 0; i < 4; i++)
                #pragma unroll
                for (int j = 0; j < 4; j++)
                    acc[i][j] = fmaf(a[i], b[j], acc[i][j]);
        }
        __syncthreads();
    }

    if (!do_sm) {
        #pragma unroll
        for (int i = 0; i < 4; i++) {
            float4 v = make_float4(acc[i][0], acc[i][1], acc[i][2], acc[i][3]);
            *reinterpret_cast<float4*>(&O[(size_t)(bm + ty * 4 + i) * DIM + bn + tx * 4]) = v;
        }
        return;
    }

    // Softmax over 32-column head groups (a 64-wide tile holds 2 full heads).
    #pragma unroll
    for (int i = 0; i < 4; i++)
        #pragma unroll
        for (int j = 0; j < 4; j++)
            T[ty * 4 + i][tx * 4 + j] = acc[i][j];
    __syncthreads();
    if (tid < 128) {
        int r = tid >> 1;
        int g = (tid & 1) * 32;
        float mx = -1e30f;
        #pragma unroll
        for (int c = 0; c < 32; c++) mx = fmaxf(mx, T[r][g + c]);
        float e[32];
        float s = 0.f;
        #pragma unroll
        for (int c = 0; c < 32; c++) { e[c] = expf(T[r][g + c] - mx); s += e[c]; }
        float inv = 1.f / s;
        #pragma unroll
        for (int c = 0; c < 32; c++)
            O[(size_t)(bm + r) * DIM + bn + g + c] = e[c] * inv;
    }
}

// ---------------------------------------------------------------------------
// Kernel 2: per-chunk KV outer-product sums  S_c[d][e] = sum_{l in chunk} K[l,d]*V[l,e]
// One block per (n,h,chunk). 256 threads, 4 outputs each.
// ---------------------------------------------------------------------------
__global__ __launch_bounds__(256) void chunk_kv_kernel()
{
    const int b = blockIdx.x;
    const int c = b & (N_CHUNK - 1);
    const int h = (b >> 6) & (N_H - 1);
    const int n = b >> 10;

    __shared__ float Ks[CHUNK][D_H];
    __shared__ float Vs[CHUNK][D_H];

    const int tid = threadIdx.x;
    {
        int l = tid >> 3;
        int d0 = (tid & 7) * 4;
        size_t base = (size_t)(n * L_SEQ + c * CHUNK + l) * DIM + h * D_H + d0;
        *reinterpret_cast<float4*>(&Ks[l][d0]) = *reinterpret_cast<const float4*>(&g_K[base]);
        *reinterpret_cast<float4*>(&Vs[l][d0]) = *reinterpret_cast<const float4*>(&g_V[base]);
    }
    __syncthreads();

    const int d  = tid >> 3;
    const int e0 = (tid & 7) * 4;
    float acc[4] = {};
    #pragma unroll
    for (int l = 0; l < CHUNK; l++) {
        float kv = Ks[l][d];
        float4 v4 = *reinterpret_cast<const float4*>(&Vs[l][e0]);
        acc[0] = fmaf(kv, v4.x, acc[0]);
        acc[1] = fmaf(kv, v4.y, acc[1]);
        acc[2] = fmaf(kv, v4.z, acc[2]);
        acc[3] = fmaf(kv, v4.w, acc[3]);
    }
    size_t sp = ((size_t)((n * N_H + h) * N_CHUNK + c) * D_H + d) * D_H + e0;
    *reinterpret_cast<float4*>(&g_S[sp]) = make_float4(acc[0], acc[1], acc[2], acc[3]);
}

// ---------------------------------------------------------------------------
// Kernel 3: exclusive prefix-scan of chunk states over the chunk axis.
// 65536 independent lanes (n,h,d,e), each scans 64 chunks sequentially.
// ---------------------------------------------------------------------------
__global__ __launch_bounds__(256) void scan_kernel()
{
    const int lane = blockIdx.x * blockDim.x + threadIdx.x;   // 0..65535
    const int idx = lane & (D_H * D_H - 1);                   // d*32+e
    const int nh  = lane >> 10;                               // 0..63
    float* base = &g_S[(size_t)nh * N_CHUNK * D_H * D_H + idx];
    float run = 0.f;
    #pragma unroll 8
    for (int c = 0; c < N_CHUNK; c++) {
        float v = base[(size_t)c * D_H * D_H];
        base[(size_t)c * D_H * D_H] = run;    // exclusive prefix
        run += v;
    }
}

// ---------------------------------------------------------------------------
// Kernel 4: per-chunk output
//   out[i,e] = sum_d Q[i,d]*Sprev[d,e] + sum_{j<=i} (Q_i . K_j) * V[j,e]
// One block per (n,h,chunk).
// ---------------------------------------------------------------------------
__global__ __launch_bounds__(256) void out_kernel(float* __restrict__ out)
{
    const int b = blockIdx.x;
    const int c = b & (N_CHUNK - 1);
    const int h = (b >> 6) & (N_H - 1);
    const int n = b >> 10;

    __shared__ float Qs[CHUNK][33];
    __shared__ float Ks[CHUNK][33];
    __shared__ float Vs[CHUNK][D_H];
    __shared__ float Sp[D_H][D_H];
    __shared__ float Am[CHUNK][33];

    const int tid = threadIdx.x;
    {
        int l = tid >> 3;
        int d0 = (tid & 7) * 4;
        size_t base = (size_t)(n * L_SEQ + c * CHUNK + l) * DIM + h * D_H + d0;
        float4 q4 = *reinterpret_cast<const float4*>(&g_Q[base]);
        Qs[l][d0 + 0] = q4.x; Qs[l][d0 + 1] = q4.y; Qs[l][d0 + 2] = q4.z; Qs[l][d0 + 3] = q4.w;
        float4 k4 = *reinterpret_cast<const float4*>(&g_K[base]);
        Ks[l][d0 + 0] = k4.x; Ks[l][d0 + 1] = k4.y; Ks[l][d0 + 2] = k4.z; Ks[l][d0 + 3] = k4.w;
        *reinterpret_cast<float4*>(&Vs[l][d0]) = *reinterpret_cast<const float4*>(&g_V[base]);
        size_t sb = (size_t)((n * N_H + h) * N_CHUNK + c) * D_H * D_H + l * D_H + d0;
        *reinterpret_cast<float4*>(&Sp[l][d0]) = *reinterpret_cast<const float4*>(&g_S[sb]);
    }
    __syncthreads();

    const int i  = tid >> 3;
    const int j0 = (tid & 7) * 4;

    // A[i][j] = Q_i . K_j  (causal inclusive mask)
    float a[4] = {};
    #pragma unroll
    for (int d = 0; d < D_H; d++) {
        float q = Qs[i][d];
        a[0] = fmaf(q, Ks[j0 + 0][d], a[0]);
        a[1] = fmaf(q, Ks[j0 + 1][d], a[1]);
        a[2] = fmaf(q, Ks[j0 + 2][d], a[2]);
        a[3] = fmaf(q, Ks[j0 + 3][d], a[3]);
    }
    #pragma unroll
    for (int jj = 0; jj < 4; jj++)
        Am[i][j0 + jj] = (j0 + jj <= i) ? a[jj] : 0.f;
    __syncthreads();

    // out[i][e0..e0+3] = Q_i @ Sp + A_i @ V
    const int e0 = j0;
    float o[4] = {};
    #pragma unroll
    for (int d = 0; d < D_H; d++) {
        float q = Qs[i][d];
        float4 s4 = *reinterpret_cast<const float4*>(&Sp[d][e0]);
        o[0] = fmaf(q, s4.x, o[0]);
        o[1] = fmaf(q, s4.y, o[1]);
        o[2] = fmaf(q, s4.z, o[2]);
        o[3] = fmaf(q, s4.w, o[3]);
    }
    #pragma unroll
    for (int j = 0; j < CHUNK; j++) {
        float av = Am[i][j];
        float4 v4 = *reinterpret_cast<const float4*>(&Vs[j][e0]);
        o[0] = fmaf(av, v4.x, o[0]);
        o[1] = fmaf(av, v4.y, o[1]);
        o[2] = fmaf(av, v4.z, o[2]);
        o[3] = fmaf(av, v4.w, o[3]);
    }
    size_t ob = (size_t)(n * L_SEQ + c * CHUNK + i) * DIM + h * D_H + e0;
    *reinterpret_cast<float4*>(&out[ob]) = make_float4(o[0], o[1], o[2], o[3]);
}

// ---------------------------------------------------------------------------
extern "C" void kernel_launch(void* const* d_in, const int* in_sizes, int n_in,
                              void* d_out, int out_size)
{
    const float* query = (const float*)d_in[0];
    const float* key   = (const float*)d_in[1];
    const float* Wq    = (const float*)d_in[2];
    const float* Wk    = (const float*)d_in[3];
    const float* Wv    = (const float*)d_in[4];
    float* out = (float*)d_out;

    dim3 g1(DIM / 64, TOT_ROWS / 64, 3);    // (8, 128, 3)
    proj_kernel<<<g1, 256>>>(query, key, Wq, Wk, Wv);
    chunk_kv_kernel<<<N_B * N_H * N_CHUNK, 256>>>();
    scan_kernel<<<(N_B * N_H * D_H * D_H) / 256, 256>>>();
    out_kernel<<<N_B * N_H * N_CHUNK, 256>>>(out);
}

// round 4
// speedup vs baseline: 2.0869x; 2.0869x over previous
#include <cuda_runtime.h>
#include <cuda_bf16.h>
#include <cstdint>

#define N_B   4
#define L_SEQ 2048
#define N_H   16
#define D_H   32
#define DIM   512
#define CHUNK 32
#define N_CHUNK (L_SEQ / CHUNK)     // 64
#define TOT_ROWS (N_B * L_SEQ)      // 8192

// ---------------- device scratch (allocation-free rule) ----------------
__device__ float g_Q[TOT_ROWS * DIM];
__device__ float g_K[TOT_ROWS * DIM];
__device__ float g_V[TOT_ROWS * DIM];
__device__ float g_S[N_B * N_H * N_CHUNK * D_H * D_H];

// bf16 hi/lo split operands (raw u16)
__device__ unsigned short bQh[TOT_ROWS * DIM];
__device__ unsigned short bQl[TOT_ROWS * DIM];
__device__ unsigned short bKh[TOT_ROWS * DIM];
__device__ unsigned short bKl[TOT_ROWS * DIM];
__device__ unsigned short bWh[3][DIM * DIM];
__device__ unsigned short bWl[3][DIM * DIM];

// ---------------- helpers ----------------
__device__ __forceinline__ uint32_t smem_u32(const void* p) {
    uint32_t a;
    asm("{ .reg .u64 t; cvta.to.shared.u64 t, %1; cvt.u32.u64 %0, t; }" : "=r"(a) : "l"(p));
    return a;
}
__device__ __forceinline__ void cp16(uint32_t dst, const void* src) {
    asm volatile("cp.async.cg.shared.global [%0], [%1], 16;" :: "r"(dst), "l"(src));
}
__device__ __forceinline__ void cp_commit() { asm volatile("cp.async.commit_group;" ::: "memory"); }
template<int N> __device__ __forceinline__ void cp_wait() {
    asm volatile("cp.async.wait_group %0;" :: "n"(N) : "memory");
}

__device__ __forceinline__ void ldsm4(uint32_t* r, uint32_t a) {
    asm volatile("ldmatrix.sync.aligned.m8n8.x4.shared.b16 {%0,%1,%2,%3}, [%4];"
                 : "=r"(r[0]), "=r"(r[1]), "=r"(r[2]), "=r"(r[3]) : "r"(a));
}
__device__ __forceinline__ void mma16816(float* d, const uint32_t* a, uint32_t b0, uint32_t b1) {
    asm volatile(
        "mma.sync.aligned.m16n8k16.row.col.f32.bf16.bf16.f32 "
        "{%0,%1,%2,%3}, {%4,%5,%6,%7}, {%8,%9}, {%0,%1,%2,%3};"
        : "+f"(d[0]), "+f"(d[1]), "+f"(d[2]), "+f"(d[3])
        : "r"(a[0]), "r"(a[1]), "r"(a[2]), "r"(a[3]), "r"(b0), "r"(b1));
}

__device__ __forceinline__ unsigned short f2bfu(float x) {
    __nv_bfloat16 b = __float2bfloat16(x);
    return *reinterpret_cast<unsigned short*>(&b);
}
__device__ __forceinline__ float bfu2f(unsigned short u) {
    __nv_bfloat16 b = *reinterpret_cast<__nv_bfloat16*>(&u);
    return __bfloat162float(b);
}

// ---------------------------------------------------------------------------
// Kernel 0: fp32 -> bf16 hi/lo split
// ---------------------------------------------------------------------------
#define NQ4 (TOT_ROWS * DIM / 4)
#define NW4 (DIM * DIM / 4)

__global__ __launch_bounds__(256) void convert_kernel(
    const float* __restrict__ q, const float* __restrict__ k,
    const float* __restrict__ wq, const float* __restrict__ wk,
    const float* __restrict__ wv)
{
    int idx = blockIdx.x * 256 + threadIdx.x;
    const float* src;
    unsigned short *dh, *dl;
    int rel;
    if (idx < NQ4)            { src = q;  dh = bQh;    dl = bQl;    rel = idx; }
    else if (idx < 2 * NQ4)   { src = k;  dh = bKh;    dl = bKl;    rel = idx - NQ4; }
    else if (idx < 2 * NQ4 + NW4)     { src = wq; dh = bWh[0]; dl = bWl[0]; rel = idx - 2 * NQ4; }
    else if (idx < 2 * NQ4 + 2 * NW4) { src = wk; dh = bWh[1]; dl = bWl[1]; rel = idx - 2 * NQ4 - NW4; }
    else                               { src = wv; dh = bWh[2]; dl = bWl[2]; rel = idx - 2 * NQ4 - 2 * NW4; }

    float4 v = reinterpret_cast<const float4*>(src)[rel];
    float x[4] = {v.x, v.y, v.z, v.w};
    unsigned short h[4], l[4];
    #pragma unroll
    for (int j = 0; j < 4; j++) {
        h[j] = f2bfu(x[j]);
        l[j] = f2bfu(x[j] - bfu2f(h[j]));
    }
    uint2 hp = make_uint2((uint32_t)h[0] | ((uint32_t)h[1] << 16),
                          (uint32_t)h[2] | ((uint32_t)h[3] << 16));
    uint2 lp = make_uint2((uint32_t)l[0] | ((uint32_t)l[1] << 16),
                          (uint32_t)l[2] | ((uint32_t)l[3] << 16));
    reinterpret_cast<uint2*>(dh)[rel] = hp;
    reinterpret_cast<uint2*>(dl)[rel] = lp;
}

// ---------------------------------------------------------------------------
// Kernel 1: HMMA projection GEMM (mma.sync bf16, 3-pass hi/lo split).
// CTA 128x128, 8 warps of 64x32 (warp N = one head), BK=32, double buffer.
// smem rows padded to 80B (40 halfwords) -> conflict-free ldmatrix.
// ---------------------------------------------------------------------------
#define SR 40                         // smem row stride in halfwords
#define TILE_HW (128 * SR)            // 5120 halfwords = 10240 B per tile
#define TILE_B  (TILE_HW * 2)
#define SMEM_BYTES (8 * TILE_B)       // Ah,Al,Bh,Bl x 2 buffers = 81920

__global__ __launch_bounds__(256) void proj_mma_kernel()
{
    extern __shared__ char smem_raw[];
    const uint32_t sb = smem_u32(smem_raw);
    const int tid  = threadIdx.x;
    const int wid  = tid >> 5;
    const int lane = tid & 31;
    const int warp_m = wid & 1;       // 0..1
    const int warp_n = wid >> 1;      // 0..3

    const int z  = blockIdx.z;
    const int bm = blockIdx.y * 128;
    const int bn = blockIdx.x * 128;
    const unsigned short* Ah = (z == 0) ? bQh : bKh;
    const unsigned short* Al = (z == 0) ? bQl : bKl;
    const unsigned short* Bh = bWh[z];
    const unsigned short* Bl = bWl[z];
    float* O = (z == 0) ? g_Q : (z == 1 ? g_K : g_V);

    auto tA = [&](int hl, int buf) { return sb + (uint32_t)(hl * 2 + buf) * TILE_B; };
    auto tB = [&](int hl, int buf) { return sb + (uint32_t)(4 + hl * 2 + buf) * TILE_B; };

    // async-load one BK=32 chunk into buffer buf
    auto prefetch = [&](int c, int buf) {
        const int k0 = c * 32;
        #pragma unroll
        for (int i = 0; i < 2; i++) {
            int idx = tid + 256 * i;
            int row = idx >> 2, seg = idx & 3;
            uint32_t doff = (uint32_t)(row * SR + seg * 8) * 2;
            const unsigned short* sAh = Ah + (size_t)(bm + row) * DIM + k0 + seg * 8;
            const unsigned short* sAl = Al + (size_t)(bm + row) * DIM + k0 + seg * 8;
            const unsigned short* sBh = Bh + (size_t)(bn + row) * DIM + k0 + seg * 8;
            const unsigned short* sBl = Bl + (size_t)(bn + row) * DIM + k0 + seg * 8;
            cp16(tA(0, buf) + doff, sAh);
            cp16(tA(1, buf) + doff, sAl);
            cp16(tB(0, buf) + doff, sBh);
            cp16(tB(1, buf) + doff, sBl);
        }
        cp_commit();
    };

    float acc[4][4][4] = {};          // [mtile][ntile][frag]

    prefetch(0, 0);

    const int jA = lane >> 3;
    const int rA = lane & 7;

    for (int c = 0; c < 16; c++) {
        const int buf = c & 1;
        // FIX (R3 race): issue the NEXT chunk's loads FIRST, so wait_group<1>
        // actually forces completion of chunk c's group (otherwise only one
        // group is pending and the wait is a no-op -> MMA reads in-flight smem).
        if (c + 1 < 16) {
            prefetch(c + 1, (c + 1) & 1);
            cp_wait<1>();
        } else {
            cp_wait<0>();
        }
        __syncthreads();

        #pragma unroll
        for (int ks = 0; ks < 2; ks++) {
            uint32_t fAh[4][4], fAl[4][4], fBh[2][4], fBl[2][4];
            #pragma unroll
            for (int mt = 0; mt < 4; mt++) {
                uint32_t off = (uint32_t)((warp_m * 64 + mt * 16 + (jA & 1) * 8 + rA) * SR
                                          + ks * 16 + (jA >> 1) * 8) * 2;
                ldsm4(fAh[mt], tA(0, buf) + off);
                ldsm4(fAl[mt], tA(1, buf) + off);
            }
            #pragma unroll
            for (int g = 0; g < 2; g++) {
                uint32_t off = (uint32_t)((warp_n * 32 + g * 16 + (jA & 1) * 8 + rA) * SR
                                          + ks * 16 + (jA >> 1) * 8) * 2;
                ldsm4(fBh[g], tB(0, buf) + off);
                ldsm4(fBl[g], tB(1, buf) + off);
            }
            #pragma unroll
            for (int mt = 0; mt < 4; mt++)
                #pragma unroll
                for (int nt = 0; nt < 4; nt++) {
                    int g = nt >> 1, s = nt & 1;
                    mma16816(acc[mt][nt], fAh[mt], fBh[g][s], fBh[g][s + 2]);
                    mma16816(acc[mt][nt], fAh[mt], fBl[g][s], fBl[g][s + 2]);
                    mma16816(acc[mt][nt], fAl[mt], fBh[g][s], fBh[g][s + 2]);
                }
        }
        __syncthreads();
    }

    // Epilogue: softmax per row over this warp's 32-col head (z<2), then store.
    const int qlane = lane & 3;
    #pragma unroll
    for (int mt = 0; mt < 4; mt++) {
        #pragma unroll
        for (int rh = 0; rh < 2; rh++) {
            float v[4][2];
            #pragma unroll
            for (int nt = 0; nt < 4; nt++) {
                v[nt][0] = acc[mt][nt][2 * rh + 0];
                v[nt][1] = acc[mt][nt][2 * rh + 1];
            }
            if (z < 2) {
                float mx = v[0][0];
                #pragma unroll
                for (int nt = 0; nt < 4; nt++) {
                    mx = fmaxf(mx, v[nt][0]);
                    mx = fmaxf(mx, v[nt][1]);
                }
                mx = fmaxf(mx, __shfl_xor_sync(0xffffffffu, mx, 1));
                mx = fmaxf(mx, __shfl_xor_sync(0xffffffffu, mx, 2));
                float s = 0.f;
                #pragma unroll
                for (int nt = 0; nt < 4; nt++) {
                    v[nt][0] = expf(v[nt][0] - mx);
                    v[nt][1] = expf(v[nt][1] - mx);
                    s += v[nt][0] + v[nt][1];
                }
                s += __shfl_xor_sync(0xffffffffu, s, 1);
                s += __shfl_xor_sync(0xffffffffu, s, 2);
                float inv = 1.f / s;
                #pragma unroll
                for (int nt = 0; nt < 4; nt++) { v[nt][0] *= inv; v[nt][1] *= inv; }
            }
            int row = bm + warp_m * 64 + mt * 16 + (lane >> 2) + rh * 8;
            #pragma unroll
            for (int nt = 0; nt < 4; nt++) {
                int col = bn + warp_n * 32 + nt * 8 + 2 * qlane;
                *reinterpret_cast<float2*>(&O[(size_t)row * DIM + col]) =
                    make_float2(v[nt][0], v[nt][1]);
            }
        }
    }
}

// ---------------------------------------------------------------------------
// Kernel 2: per-chunk KV outer-product sums
// ---------------------------------------------------------------------------
__global__ __launch_bounds__(256) void chunk_kv_kernel()
{
    const int b = blockIdx.x;
    const int c = b & (N_CHUNK - 1);
    const int h = (b >> 6) & (N_H - 1);
    const int n = b >> 10;

    __shared__ float Ks[CHUNK][D_H];
    __shared__ float Vs[CHUNK][D_H];

    const int tid = threadIdx.x;
    {
        int l = tid >> 3;
        int d0 = (tid & 7) * 4;
        size_t base = (size_t)(n * L_SEQ + c * CHUNK + l) * DIM + h * D_H + d0;
        *reinterpret_cast<float4*>(&Ks[l][d0]) = *reinterpret_cast<const float4*>(&g_K[base]);
        *reinterpret_cast<float4*>(&Vs[l][d0]) = *reinterpret_cast<const float4*>(&g_V[base]);
    }
    __syncthreads();

    const int d  = tid >> 3;
    const int e0 = (tid & 7) * 4;
    float acc[4] = {};
    #pragma unroll
    for (int l = 0; l < CHUNK; l++) {
        float kv = Ks[l][d];
        float4 v4 = *reinterpret_cast<const float4*>(&Vs[l][e0]);
        acc[0] = fmaf(kv, v4.x, acc[0]);
        acc[1] = fmaf(kv, v4.y, acc[1]);
        acc[2] = fmaf(kv, v4.z, acc[2]);
        acc[3] = fmaf(kv, v4.w, acc[3]);
    }
    size_t sp = ((size_t)((n * N_H + h) * N_CHUNK + c) * D_H + d) * D_H + e0;
    *reinterpret_cast<float4*>(&g_S[sp]) = make_float4(acc[0], acc[1], acc[2], acc[3]);
}

// ---------------------------------------------------------------------------
// Kernel 3: exclusive prefix-scan over chunks
// ---------------------------------------------------------------------------
__global__ __launch_bounds__(256) void scan_kernel()
{
    const int lane = blockIdx.x * blockDim.x + threadIdx.x;
    const int idx = lane & (D_H * D_H - 1);
    const int nh  = lane >> 10;
    float* base = &g_S[(size_t)nh * N_CHUNK * D_H * D_H + idx];
    float run = 0.f;
    #pragma unroll 8
    for (int c = 0; c < N_CHUNK; c++) {
        float v = base[(size_t)c * D_H * D_H];
        base[(size_t)c * D_H * D_H] = run;
        run += v;
    }
}

// ---------------------------------------------------------------------------
// Kernel 4: per-chunk output (intra-chunk causal + prefix state)
// ---------------------------------------------------------------------------
__global__ __launch_bounds__(256) void out_kernel(float* __restrict__ out)
{
    const int b = blockIdx.x;
    const int c = b & (N_CHUNK - 1);
    const int h = (b >> 6) & (N_H - 1);
    const int n = b >> 10;

    __shared__ float Qs[CHUNK][33];
    __shared__ float Ks[CHUNK][33];
    __shared__ float Vs[CHUNK][D_H];
    __shared__ float Sp[D_H][D_H];
    __shared__ float Am[CHUNK][33];

    const int tid = threadIdx.x;
    {
        int l = tid >> 3;
        int d0 = (tid & 7) * 4;
        size_t base = (size_t)(n * L_SEQ + c * CHUNK + l) * DIM + h * D_H + d0;
        float4 q4 = *reinterpret_cast<const float4*>(&g_Q[base]);
        Qs[l][d0 + 0] = q4.x; Qs[l][d0 + 1] = q4.y; Qs[l][d0 + 2] = q4.z; Qs[l][d0 + 3] = q4.w;
        float4 k4 = *reinterpret_cast<const float4*>(&g_K[base]);
        Ks[l][d0 + 0] = k4.x; Ks[l][d0 + 1] = k4.y; Ks[l][d0 + 2] = k4.z; Ks[l][d0 + 3] = k4.w;
        *reinterpret_cast<float4*>(&Vs[l][d0]) = *reinterpret_cast<const float4*>(&g_V[base]);
        size_t sb2 = (size_t)((n * N_H + h) * N_CHUNK + c) * D_H * D_H + l * D_H + d0;
        *reinterpret_cast<float4*>(&Sp[l][d0]) = *reinterpret_cast<const float4*>(&g_S[sb2]);
    }
    __syncthreads();

    const int i  = tid >> 3;
    const int j0 = (tid & 7) * 4;

    float a[4] = {};
    #pragma unroll
    for (int d = 0; d < D_H; d++) {
        float q = Qs[i][d];
        a[0] = fmaf(q, Ks[j0 + 0][d], a[0]);
        a[1] = fmaf(q, Ks[j0 + 1][d], a[1]);
        a[2] = fmaf(q, Ks[j0 + 2][d], a[2]);
        a[3] = fmaf(q, Ks[j0 + 3][d], a[3]);
    }
    #pragma unroll
    for (int jj = 0; jj < 4; jj++)
        Am[i][j0 + jj] = (j0 + jj <= i) ? a[jj] : 0.f;
    __syncthreads();

    const int e0 = j0;
    float o[4] = {};
    #pragma unroll
    for (int d = 0; d < D_H; d++) {
        float q = Qs[i][d];
        float4 s4 = *reinterpret_cast<const float4*>(&Sp[d][e0]);
        o[0] = fmaf(q, s4.x, o[0]);
        o[1] = fmaf(q, s4.y, o[1]);
        o[2] = fmaf(q, s4.z, o[2]);
        o[3] = fmaf(q, s4.w, o[3]);
    }
    #pragma unroll
    for (int j = 0; j < CHUNK; j++) {
        float av = Am[i][j];
        float4 v4 = *reinterpret_cast<const float4*>(&Vs[j][e0]);
        o[0] = fmaf(av, v4.x, o[0]);
        o[1] = fmaf(av, v4.y, o[1]);
        o[2] = fmaf(av, v4.z, o[2]);
        o[3] = fmaf(av, v4.w, o[3]);
    }
    size_t ob = (size_t)(n * L_SEQ + c * CHUNK + i) * DIM + h * D_H + e0;
    *reinterpret_cast<float4*>(&out[ob]) = make_float4(o[0], o[1], o[2], o[3]);
}

// ---------------------------------------------------------------------------
extern "C" void kernel_launch(void* const* d_in, const int* in_sizes, int n_in,
                              void* d_out, int out_size)
{
    const float* query = (const float*)d_in[0];
    const float* key   = (const float*)d_in[1];
    const float* Wq    = (const float*)d_in[2];
    const float* Wk    = (const float*)d_in[3];
    const float* Wv    = (const float*)d_in[4];
    float* out = (float*)d_out;

    cudaFuncSetAttribute(proj_mma_kernel,
                         cudaFuncAttributeMaxDynamicSharedMemorySize, SMEM_BYTES);

    int conv_blocks = (2 * NQ4 + 3 * NW4) / 256;
    convert_kernel<<<conv_blocks, 256>>>(query, key, Wq, Wk, Wv);

    dim3 gp(DIM / 128, TOT_ROWS / 128, 3);      // (4, 64, 3) = 768 CTAs
    proj_mma_kernel<<<gp, 256, SMEM_BYTES>>>();

    chunk_kv_kernel<<<N_B * N_H * N_CHUNK, 256>>>();
    scan_kernel<<<(N_B * N_H * D_H * D_H) / 256, 256>>>();
    out_kernel<<<N_B * N_H * N_CHUNK, 256>>>(out);
}

// round 5
// speedup vs baseline: 2.6408x; 1.2654x over previous
#include <cuda_runtime.h>
#include <cuda_fp16.h>
#include <cstdint>

#define N_B   4
#define L_SEQ 2048
#define N_H   16
#define D_H   32
#define DIM   512
#define CHUNK 32
#define N_CHUNK (L_SEQ / CHUNK)     // 64
#define TOT_ROWS (N_B * L_SEQ)      // 8192

// ---------------- device scratch (allocation-free rule) ----------------
__device__ float g_Q[TOT_ROWS * DIM];
__device__ float g_K[TOT_ROWS * DIM];
__device__ float g_V[TOT_ROWS * DIM];
__device__ float g_S[N_B * N_H * N_CHUNK * D_H * D_H];

// fp16 operands: activations hi-only; weights hi/lo split
__device__ __half hQ[TOT_ROWS * DIM];
__device__ __half hK[TOT_ROWS * DIM];
__device__ __half hWh[3][DIM * DIM];
__device__ __half hWl[3][DIM * DIM];

// ---------------- helpers ----------------
__device__ __forceinline__ uint32_t smem_u32(const void* p) {
    uint32_t a;
    asm("{ .reg .u64 t; cvta.to.shared.u64 t, %1; cvt.u32.u64 %0, t; }" : "=r"(a) : "l"(p));
    return a;
}
__device__ __forceinline__ void cp16(uint32_t dst, const void* src) {
    asm volatile("cp.async.cg.shared.global [%0], [%1], 16;" :: "r"(dst), "l"(src));
}
__device__ __forceinline__ void cp_commit() { asm volatile("cp.async.commit_group;" ::: "memory"); }
template<int N> __device__ __forceinline__ void cp_wait() {
    asm volatile("cp.async.wait_group %0;" :: "n"(N) : "memory");
}
__device__ __forceinline__ void ldsm4(uint32_t* r, uint32_t a) {
    asm volatile("ldmatrix.sync.aligned.m8n8.x4.shared.b16 {%0,%1,%2,%3}, [%4];"
                 : "=r"(r[0]), "=r"(r[1]), "=r"(r[2]), "=r"(r[3]) : "r"(a));
}
__device__ __forceinline__ void mma16816(float* d, const uint32_t* a, uint32_t b0, uint32_t b1) {
    asm volatile(
        "mma.sync.aligned.m16n8k16.row.col.f32.f16.f16.f32 "
        "{%0,%1,%2,%3}, {%4,%5,%6,%7}, {%8,%9}, {%0,%1,%2,%3};"
        : "+f"(d[0]), "+f"(d[1]), "+f"(d[2]), "+f"(d[3])
        : "r"(a[0]), "r"(a[1]), "r"(a[2]), "r"(a[3]), "r"(b0), "r"(b1));
}

// ---------------------------------------------------------------------------
// Kernel 0: fp32 -> fp16 (activations: hi only; weights: hi/lo split)
// ---------------------------------------------------------------------------
#define NQ4 (TOT_ROWS * DIM / 4)
#define NW4 (DIM * DIM / 4)

__global__ __launch_bounds__(256) void convert_kernel(
    const float* __restrict__ q, const float* __restrict__ k,
    const float* __restrict__ wq, const float* __restrict__ wk,
    const float* __restrict__ wv)
{
    int idx = blockIdx.x * 256 + threadIdx.x;
    if (idx < 2 * NQ4) {
        const float* src = (idx < NQ4) ? q : k;
        __half* dst = (idx < NQ4) ? hQ : hK;
        int rel = (idx < NQ4) ? idx : idx - NQ4;
        float4 v = reinterpret_cast<const float4*>(src)[rel];
        __half2 a = make_half2(__float2half_rn(v.x), __float2half_rn(v.y));
        __half2 b = make_half2(__float2half_rn(v.z), __float2half_rn(v.w));
        reinterpret_cast<__half2*>(dst)[rel * 2]     = a;
        reinterpret_cast<__half2*>(dst)[rel * 2 + 1] = b;
    } else {
        int t = idx - 2 * NQ4;
        int w = t / NW4;                 // 0..2
        int rel = t - w * NW4;
        const float* src = (w == 0) ? wq : (w == 1 ? wk : wv);
        float4 v = reinterpret_cast<const float4*>(src)[rel];
        float x[4] = {v.x, v.y, v.z, v.w};
        __half h[4], l[4];
        #pragma unroll
        for (int j = 0; j < 4; j++) {
            h[j] = __float2half_rn(x[j]);
            l[j] = __float2half_rn(x[j] - __half2float(h[j]));
        }
        reinterpret_cast<__half2*>(hWh[w])[rel * 2]     = make_half2(h[0], h[1]);
        reinterpret_cast<__half2*>(hWh[w])[rel * 2 + 1] = make_half2(h[2], h[3]);
        reinterpret_cast<__half2*>(hWl[w])[rel * 2]     = make_half2(l[0], l[1]);
        reinterpret_cast<__half2*>(hWl[w])[rel * 2 + 1] = make_half2(l[2], l[3]);
    }
}

// ---------------------------------------------------------------------------
// Kernel 1: HMMA projection GEMM (fp16, 2-pass: Ah*Bh + Ah*Bl).
// CTA 128x128, 8 warps of 64x32 (warp N = one head), BK=32, double buffer.
// ---------------------------------------------------------------------------
#define SR 40                         // smem row stride in halfwords (80B)
#define TILE_HW (128 * SR)
#define TILE_B  (TILE_HW * 2)         // 10240 B
#define SMEM_BYTES (6 * TILE_B)       // A x2, Bh x2, Bl x2 = 61440

__global__ __launch_bounds__(256, 2) void proj_mma_kernel()
{
    extern __shared__ char smem_raw[];
    const uint32_t sb = smem_u32(smem_raw);
    const int tid  = threadIdx.x;
    const int wid  = tid >> 5;
    const int lane = tid & 31;
    const int warp_m = wid & 1;
    const int warp_n = wid >> 1;

    const int z  = blockIdx.z;
    const int bm = blockIdx.y * 128;
    const int bn = blockIdx.x * 128;
    const __half* A  = (z == 0) ? hQ : hK;
    const __half* Bh = hWh[z];
    const __half* Bl = hWl[z];
    float* O = (z == 0) ? g_Q : (z == 1 ? g_K : g_V);

    auto tA  = [&](int buf) { return sb + (uint32_t)buf * TILE_B; };
    auto tBh = [&](int buf) { return sb + (uint32_t)(2 + buf) * TILE_B; };
    auto tBl = [&](int buf) { return sb + (uint32_t)(4 + buf) * TILE_B; };

    auto prefetch = [&](int c, int buf) {
        const int k0 = c * 32;
        #pragma unroll
        for (int i = 0; i < 2; i++) {
            int idx = tid + 256 * i;
            int row = idx >> 2, seg = idx & 3;
            uint32_t doff = (uint32_t)(row * SR + seg * 8) * 2;
            cp16(tA(buf)  + doff, A  + (size_t)(bm + row) * DIM + k0 + seg * 8);
            cp16(tBh(buf) + doff, Bh + (size_t)(bn + row) * DIM + k0 + seg * 8);
            cp16(tBl(buf) + doff, Bl + (size_t)(bn + row) * DIM + k0 + seg * 8);
        }
        cp_commit();
    };

    float acc[4][4][4] = {};
    prefetch(0, 0);

    const int jA = lane >> 3;
    const int rA = lane & 7;

    for (int c = 0; c < 16; c++) {
        const int buf = c & 1;
        if (c + 1 < 16) {
            prefetch(c + 1, (c + 1) & 1);
            cp_wait<1>();
        } else {
            cp_wait<0>();
        }
        __syncthreads();

        #pragma unroll
        for (int ks = 0; ks < 2; ks++) {
            uint32_t fA[4][4], fBh_[2][4], fBl_[2][4];
            #pragma unroll
            for (int mt = 0; mt < 4; mt++) {
                uint32_t off = (uint32_t)((warp_m * 64 + mt * 16 + (jA & 1) * 8 + rA) * SR
                                          + ks * 16 + (jA >> 1) * 8) * 2;
                ldsm4(fA[mt], tA(buf) + off);
            }
            #pragma unroll
            for (int g = 0; g < 2; g++) {
                uint32_t off = (uint32_t)((warp_n * 32 + g * 16 + (jA & 1) * 8 + rA) * SR
                                          + ks * 16 + (jA >> 1) * 8) * 2;
                ldsm4(fBh_[g], tBh(buf) + off);
                ldsm4(fBl_[g], tBl(buf) + off);
            }
            #pragma unroll
            for (int mt = 0; mt < 4; mt++)
                #pragma unroll
                for (int nt = 0; nt < 4; nt++) {
                    int g = nt >> 1, s = nt & 1;
                    mma16816(acc[mt][nt], fA[mt], fBh_[g][s], fBh_[g][s + 2]);
                    mma16816(acc[mt][nt], fA[mt], fBl_[g][s], fBl_[g][s + 2]);
                }
        }
        __syncthreads();
    }

    // Epilogue: per-row softmax over this warp's 32-col head (z<2), store fp32.
    const int qlane = lane & 3;
    #pragma unroll
    for (int mt = 0; mt < 4; mt++) {
        #pragma unroll
        for (int rh = 0; rh < 2; rh++) {
            float v[4][2];
            #pragma unroll
            for (int nt = 0; nt < 4; nt++) {
                v[nt][0] = acc[mt][nt][2 * rh + 0];
                v[nt][1] = acc[mt][nt][2 * rh + 1];
            }
            if (z < 2) {
                float mx = v[0][0];
                #pragma unroll
                for (int nt = 0; nt < 4; nt++) {
                    mx = fmaxf(mx, v[nt][0]);
                    mx = fmaxf(mx, v[nt][1]);
                }
                mx = fmaxf(mx, __shfl_xor_sync(0xffffffffu, mx, 1));
                mx = fmaxf(mx, __shfl_xor_sync(0xffffffffu, mx, 2));
                float s = 0.f;
                #pragma unroll
                for (int nt = 0; nt < 4; nt++) {
                    v[nt][0] = expf(v[nt][0] - mx);
                    v[nt][1] = expf(v[nt][1] - mx);
                    s += v[nt][0] + v[nt][1];
                }
                s += __shfl_xor_sync(0xffffffffu, s, 1);
                s += __shfl_xor_sync(0xffffffffu, s, 2);
                float inv = 1.f / s;
                #pragma unroll
                for (int nt = 0; nt < 4; nt++) { v[nt][0] *= inv; v[nt][1] *= inv; }
            }
            int row = bm + warp_m * 64 + mt * 16 + (lane >> 2) + rh * 8;
            #pragma unroll
            for (int nt = 0; nt < 4; nt++) {
                int col = bn + warp_n * 32 + nt * 8 + 2 * qlane;
                *reinterpret_cast<float2*>(&O[(size_t)row * DIM + col]) =
                    make_float2(v[nt][0], v[nt][1]);
            }
        }
    }
}

// ---------------------------------------------------------------------------
// Kernel 2: per-chunk KV outer-product sums
// ---------------------------------------------------------------------------
__global__ __launch_bounds__(256) void chunk_kv_kernel()
{
    const int b = blockIdx.x;
    const int c = b & (N_CHUNK - 1);
    const int h = (b >> 6) & (N_H - 1);
    const int n = b >> 10;

    __shared__ float Ks[CHUNK][D_H];
    __shared__ float Vs[CHUNK][D_H];

    const int tid = threadIdx.x;
    {
        int l = tid >> 3;
        int d0 = (tid & 7) * 4;
        size_t base = (size_t)(n * L_SEQ + c * CHUNK + l) * DIM + h * D_H + d0;
        *reinterpret_cast<float4*>(&Ks[l][d0]) = *reinterpret_cast<const float4*>(&g_K[base]);
        *reinterpret_cast<float4*>(&Vs[l][d0]) = *reinterpret_cast<const float4*>(&g_V[base]);
    }
    __syncthreads();

    const int d  = tid >> 3;
    const int e0 = (tid & 7) * 4;
    float acc[4] = {};
    #pragma unroll
    for (int l = 0; l < CHUNK; l++) {
        float kv = Ks[l][d];
        float4 v4 = *reinterpret_cast<const float4*>(&Vs[l][e0]);
        acc[0] = fmaf(kv, v4.x, acc[0]);
        acc[1] = fmaf(kv, v4.y, acc[1]);
        acc[2] = fmaf(kv, v4.z, acc[2]);
        acc[3] = fmaf(kv, v4.w, acc[3]);
    }
    size_t sp = ((size_t)((n * N_H + h) * N_CHUNK + c) * D_H + d) * D_H + e0;
    *reinterpret_cast<float4*>(&g_S[sp]) = make_float4(acc[0], acc[1], acc[2], acc[3]);
}

// ---------------------------------------------------------------------------
// Kernel 3: exclusive prefix-scan over chunks, 8-wide batched loads for MLP.
// ---------------------------------------------------------------------------
__global__ __launch_bounds__(256) void scan_kernel()
{
    const int lane = blockIdx.x * blockDim.x + threadIdx.x;
    const int idx = lane & (D_H * D_H - 1);
    const int nh  = lane >> 10;
    float* base = &g_S[(size_t)nh * N_CHUNK * D_H * D_H + idx];
    float run = 0.f;
    #pragma unroll
    for (int b = 0; b < 8; b++) {
        float v[8];
        #pragma unroll
        for (int j = 0; j < 8; j++)
            v[j] = base[(size_t)(b * 8 + j) * (D_H * D_H)];
        #pragma unroll
        for (int j = 0; j < 8; j++) {
            base[(size_t)(b * 8 + j) * (D_H * D_H)] = run;
            run += v[j];
        }
    }
}

// ---------------------------------------------------------------------------
// Kernel 4: per-chunk output. K stored d-major (Kt) -> float4 LDS in QK^T.
// ---------------------------------------------------------------------------
__global__ __launch_bounds__(256) void out_kernel(float* __restrict__ out)
{
    const int b = blockIdx.x;
    const int c = b & (N_CHUNK - 1);
    const int h = (b >> 6) & (N_H - 1);
    const int n = b >> 10;

    __shared__ float Qs[CHUNK][33];
    __shared__ float Kt[D_H][36];      // [d][j], stride 36 for aligned float4
    __shared__ float Vs[CHUNK][D_H];
    __shared__ float Sp[D_H][D_H];
    __shared__ float Am[CHUNK][33];

    const int tid = threadIdx.x;
    {
        int l = tid >> 3;
        int d0 = (tid & 7) * 4;
        size_t base = (size_t)(n * L_SEQ + c * CHUNK + l) * DIM + h * D_H + d0;
        float4 q4 = *reinterpret_cast<const float4*>(&g_Q[base]);
        Qs[l][d0 + 0] = q4.x; Qs[l][d0 + 1] = q4.y; Qs[l][d0 + 2] = q4.z; Qs[l][d0 + 3] = q4.w;
        float4 k4 = *reinterpret_cast<const float4*>(&g_K[base]);
        Kt[d0 + 0][l] = k4.x; Kt[d0 + 1][l] = k4.y; Kt[d0 + 2][l] = k4.z; Kt[d0 + 3][l] = k4.w;
        *reinterpret_cast<float4*>(&Vs[l][d0]) = *reinterpret_cast<const float4*>(&g_V[base]);
        size_t sb2 = (size_t)((n * N_H + h) * N_CHUNK + c) * D_H * D_H + l * D_H + d0;
        *reinterpret_cast<float4*>(&Sp[l][d0]) = *reinterpret_cast<const float4*>(&g_S[sb2]);
    }
    __syncthreads();

    const int i  = tid >> 3;
    const int j0 = (tid & 7) * 4;

    // A[i][j0..3] = Q_i . K_j  via d-major K: 1 broadcast + 1 LDS.128 per 4 FMA
    float a[4] = {};
    #pragma unroll
    for (int d = 0; d < D_H; d++) {
        float q = Qs[i][d];
        float4 k4 = *reinterpret_cast<const float4*>(&Kt[d][j0]);
        a[0] = fmaf(q, k4.x, a[0]);
        a[1] = fmaf(q, k4.y, a[1]);
        a[2] = fmaf(q, k4.z, a[2]);
        a[3] = fmaf(q, k4.w, a[3]);
    }
    #pragma unroll
    for (int jj = 0; jj < 4; jj++)
        Am[i][j0 + jj] = (j0 + jj <= i) ? a[jj] : 0.f;
    __syncthreads();

    const int e0 = j0;
    float o[4] = {};
    #pragma unroll
    for (int d = 0; d < D_H; d++) {
        float q = Qs[i][d];
        float4 s4 = *reinterpret_cast<const float4*>(&Sp[d][e0]);
        o[0] = fmaf(q, s4.x, o[0]);
        o[1] = fmaf(q, s4.y, o[1]);
        o[2] = fmaf(q, s4.z, o[2]);
        o[3] = fmaf(q, s4.w, o[3]);
    }
    #pragma unroll
    for (int j = 0; j < CHUNK; j++) {
        float av = Am[i][j];
        float4 v4 = *reinterpret_cast<const float4*>(&Vs[j][e0]);
        o[0] = fmaf(av, v4.x, o[0]);
        o[1] = fmaf(av, v4.y, o[1]);
        o[2] = fmaf(av, v4.z, o[2]);
        o[3] = fmaf(av, v4.w, o[3]);
    }
    size_t ob = (size_t)(n * L_SEQ + c * CHUNK + i) * DIM + h * D_H + e0;
    *reinterpret_cast<float4*>(&out[ob]) = make_float4(o[0], o[1], o[2], o[3]);
}

// ---------------------------------------------------------------------------
extern "C" void kernel_launch(void* const* d_in, const int* in_sizes, int n_in,
                              void* d_out, int out_size)
{
    const float* query = (const float*)d_in[0];
    const float* key   = (const float*)d_in[1];
    const float* Wq    = (const float*)d_in[2];
    const float* Wk    = (const float*)d_in[3];
    const float* Wv    = (const float*)d_in[4];
    float* out = (float*)d_out;

    cudaFuncSetAttribute(proj_mma_kernel,
                         cudaFuncAttributeMaxDynamicSharedMemorySize, SMEM_BYTES);

    int conv_blocks = (2 * NQ4 + 3 * NW4) / 256;
    convert_kernel<<<conv_blocks, 256>>>(query, key, Wq, Wk, Wv);

    dim3 gp(DIM / 128, TOT_ROWS / 128, 3);      // (4, 64, 3) = 768 CTAs
    proj_mma_kernel<<<gp, 256, SMEM_BYTES>>>();

    chunk_kv_kernel<<<N_B * N_H * N_CHUNK, 256>>>();
    scan_kernel<<<(N_B * N_H * D_H * D_H) / 256, 256>>>();
    out_kernel<<<N_B * N_H * N_CHUNK, 256>>>(out);
}

// round 6
// speedup vs baseline: 3.1615x; 1.1972x over previous
#include <cuda_runtime.h>
#include <cuda_fp16.h>
#include <cstdint>

#define N_B   4
#define L_SEQ 2048
#define N_H   16
#define D_H   32
#define DIM   512
#define CHUNK 32
#define N_CHUNK (L_SEQ / CHUNK)     // 64
#define TOT_ROWS (N_B * L_SEQ)      // 8192

// ---------------- device scratch (allocation-free rule) ----------------
__device__ float g_Q[TOT_ROWS * DIM];
__device__ float g_K[TOT_ROWS * DIM];
__device__ float g_V[TOT_ROWS * DIM];
__device__ float g_S[N_B * N_H * N_CHUNK * D_H * D_H];

// fp16 operands: activations hi-only; weights hi/lo split
__device__ __half hQ[TOT_ROWS * DIM];
__device__ __half hK[TOT_ROWS * DIM];
__device__ __half hWh[3][DIM * DIM];
__device__ __half hWl[3][DIM * DIM];

// ---------------- helpers ----------------
__device__ __forceinline__ uint32_t smem_u32(const void* p) {
    uint32_t a;
    asm("{ .reg .u64 t; cvta.to.shared.u64 t, %1; cvt.u32.u64 %0, t; }" : "=r"(a) : "l"(p));
    return a;
}
__device__ __forceinline__ void cp16(uint32_t dst, const void* src) {
    asm volatile("cp.async.cg.shared.global [%0], [%1], 16;" :: "r"(dst), "l"(src));
}
__device__ __forceinline__ void cp_commit() { asm volatile("cp.async.commit_group;" ::: "memory"); }
template<int N> __device__ __forceinline__ void cp_wait() {
    asm volatile("cp.async.wait_group %0;" :: "n"(N) : "memory");
}
__device__ __forceinline__ void ldsm4(uint32_t* r, uint32_t a) {
    asm volatile("ldmatrix.sync.aligned.m8n8.x4.shared.b16 {%0,%1,%2,%3}, [%4];"
                 : "=r"(r[0]), "=r"(r[1]), "=r"(r[2]), "=r"(r[3]) : "r"(a));
}
__device__ __forceinline__ void mma16816(float* d, const uint32_t* a, uint32_t b0, uint32_t b1) {
    asm volatile(
        "mma.sync.aligned.m16n8k16.row.col.f32.f16.f16.f32 "
        "{%0,%1,%2,%3}, {%4,%5,%6,%7}, {%8,%9}, {%0,%1,%2,%3};"
        : "+f"(d[0]), "+f"(d[1]), "+f"(d[2]), "+f"(d[3])
        : "r"(a[0]), "r"(a[1]), "r"(a[2]), "r"(a[3]), "r"(b0), "r"(b1));
}

// ---------------------------------------------------------------------------
// Kernel 0: fp32 -> fp16 (activations: hi only; weights: hi/lo split)
// ---------------------------------------------------------------------------
#define NQ4 (TOT_ROWS * DIM / 4)
#define NW4 (DIM * DIM / 4)

__global__ __launch_bounds__(256) void convert_kernel(
    const float* __restrict__ q, const float* __restrict__ k,
    const float* __restrict__ wq, const float* __restrict__ wk,
    const float* __restrict__ wv)
{
    int idx = blockIdx.x * 256 + threadIdx.x;
    if (idx < 2 * NQ4) {
        const float* src = (idx < NQ4) ? q : k;
        __half* dst = (idx < NQ4) ? hQ : hK;
        int rel = (idx < NQ4) ? idx : idx - NQ4;
        float4 v = reinterpret_cast<const float4*>(src)[rel];
        __half2 a = make_half2(__float2half_rn(v.x), __float2half_rn(v.y));
        __half2 b = make_half2(__float2half_rn(v.z), __float2half_rn(v.w));
        reinterpret_cast<__half2*>(dst)[rel * 2]     = a;
        reinterpret_cast<__half2*>(dst)[rel * 2 + 1] = b;
    } else {
        int t = idx - 2 * NQ4;
        int w = t / NW4;
        int rel = t - w * NW4;
        const float* src = (w == 0) ? wq : (w == 1 ? wk : wv);
        float4 v = reinterpret_cast<const float4*>(src)[rel];
        float x[4] = {v.x, v.y, v.z, v.w};
        __half h[4], l[4];
        #pragma unroll
        for (int j = 0; j < 4; j++) {
            h[j] = __float2half_rn(x[j]);
            l[j] = __float2half_rn(x[j] - __half2float(h[j]));
        }
        reinterpret_cast<__half2*>(hWh[w])[rel * 2]     = make_half2(h[0], h[1]);
        reinterpret_cast<__half2*>(hWh[w])[rel * 2 + 1] = make_half2(h[2], h[3]);
        reinterpret_cast<__half2*>(hWl[w])[rel * 2]     = make_half2(l[0], l[1]);
        reinterpret_cast<__half2*>(hWl[w])[rel * 2 + 1] = make_half2(l[2], l[3]);
    }
}

// ---------------------------------------------------------------------------
// Kernel 1: HMMA projection GEMM (fp16, 2-pass: Ah*Bh + Ah*Bl).
// CTA 128x128, 8 warps of 64x32, BK=64, double buffer, 2 CTA/SM.
// ---------------------------------------------------------------------------
#define SR 72                         // smem row stride in halfwords (144B)
#define TILE_HW (128 * SR)            // 9216 hw
#define TILE_B  (TILE_HW * 2)         // 18432 B
#define SMEM_BYTES (6 * TILE_B)       // A x2, Bh x2, Bl x2 = 110592

__global__ __launch_bounds__(256, 2) void proj_mma_kernel()
{
    extern __shared__ char smem_raw[];
    const uint32_t sb = smem_u32(smem_raw);
    const int tid  = threadIdx.x;
    const int wid  = tid >> 5;
    const int lane = tid & 31;
    const int warp_m = wid & 1;
    const int warp_n = wid >> 1;

    const int z  = blockIdx.z;
    const int bm = blockIdx.y * 128;
    const int bn = blockIdx.x * 128;
    const __half* A  = (z == 0) ? hQ : hK;
    const __half* Bh = hWh[z];
    const __half* Bl = hWl[z];
    float* O = (z == 0) ? g_Q : (z == 1 ? g_K : g_V);

    auto tA  = [&](int buf) { return sb + (uint32_t)buf * TILE_B; };
    auto tBh = [&](int buf) { return sb + (uint32_t)(2 + buf) * TILE_B; };
    auto tBl = [&](int buf) { return sb + (uint32_t)(4 + buf) * TILE_B; };

    // load one BK=64 chunk (128 rows x 64 halfs = 8 x 16B segs per row)
    auto prefetch = [&](int c, int buf) {
        const int k0 = c * 64;
        #pragma unroll
        for (int i = 0; i < 4; i++) {
            int idx = tid + 256 * i;
            int row = idx >> 3, seg = idx & 7;
            uint32_t doff = (uint32_t)(row * SR + seg * 8) * 2;
            cp16(tA(buf)  + doff, A  + (size_t)(bm + row) * DIM + k0 + seg * 8);
            cp16(tBh(buf) + doff, Bh + (size_t)(bn + row) * DIM + k0 + seg * 8);
            cp16(tBl(buf) + doff, Bl + (size_t)(bn + row) * DIM + k0 + seg * 8);
        }
        cp_commit();
    };

    float acc[4][4][4] = {};
    prefetch(0, 0);

    const int jA = lane >> 3;
    const int rA = lane & 7;

    for (int c = 0; c < 8; c++) {
        const int buf = c & 1;
        if (c + 1 < 8) {
            prefetch(c + 1, (c + 1) & 1);
            cp_wait<1>();
        } else {
            cp_wait<0>();
        }
        __syncthreads();

        #pragma unroll
        for (int ks = 0; ks < 4; ks++) {
            uint32_t fA[4][4], fBh_[2][4], fBl_[2][4];
            #pragma unroll
            for (int mt = 0; mt < 4; mt++) {
                uint32_t off = (uint32_t)((warp_m * 64 + mt * 16 + (jA & 1) * 8 + rA) * SR
                                          + ks * 16 + (jA >> 1) * 8) * 2;
                ldsm4(fA[mt], tA(buf) + off);
            }
            #pragma unroll
            for (int g = 0; g < 2; g++) {
                uint32_t off = (uint32_t)((warp_n * 32 + g * 16 + (jA & 1) * 8 + rA) * SR
                                          + ks * 16 + (jA >> 1) * 8) * 2;
                ldsm4(fBh_[g], tBh(buf) + off);
                ldsm4(fBl_[g], tBl(buf) + off);
            }
            #pragma unroll
            for (int mt = 0; mt < 4; mt++)
                #pragma unroll
                for (int nt = 0; nt < 4; nt++) {
                    int g = nt >> 1, s = nt & 1;
                    mma16816(acc[mt][nt], fA[mt], fBh_[g][s], fBh_[g][s + 2]);
                    mma16816(acc[mt][nt], fA[mt], fBl_[g][s], fBl_[g][s + 2]);
                }
        }
        __syncthreads();
    }

    // Epilogue: per-row softmax over this warp's 32-col head (z<2), store fp32.
    const int qlane = lane & 3;
    #pragma unroll
    for (int mt = 0; mt < 4; mt++) {
        #pragma unroll
        for (int rh = 0; rh < 2; rh++) {
            float v[4][2];
            #pragma unroll
            for (int nt = 0; nt < 4; nt++) {
                v[nt][0] = acc[mt][nt][2 * rh + 0];
                v[nt][1] = acc[mt][nt][2 * rh + 1];
            }
            if (z < 2) {
                float mx = v[0][0];
                #pragma unroll
                for (int nt = 0; nt < 4; nt++) {
                    mx = fmaxf(mx, v[nt][0]);
                    mx = fmaxf(mx, v[nt][1]);
                }
                mx = fmaxf(mx, __shfl_xor_sync(0xffffffffu, mx, 1));
                mx = fmaxf(mx, __shfl_xor_sync(0xffffffffu, mx, 2));
                float s = 0.f;
                #pragma unroll
                for (int nt = 0; nt < 4; nt++) {
                    v[nt][0] = expf(v[nt][0] - mx);
                    v[nt][1] = expf(v[nt][1] - mx);
                    s += v[nt][0] + v[nt][1];
                }
                s += __shfl_xor_sync(0xffffffffu, s, 1);
                s += __shfl_xor_sync(0xffffffffu, s, 2);
                float inv = 1.f / s;
                #pragma unroll
                for (int nt = 0; nt < 4; nt++) { v[nt][0] *= inv; v[nt][1] *= inv; }
            }
            int row = bm + warp_m * 64 + mt * 16 + (lane >> 2) + rh * 8;
            #pragma unroll
            for (int nt = 0; nt < 4; nt++) {
                int col = bn + warp_n * 32 + nt * 8 + 2 * qlane;
                *reinterpret_cast<float2*>(&O[(size_t)row * DIM + col]) =
                    make_float2(v[nt][0], v[nt][1]);
            }
        }
    }
}

// ---------------------------------------------------------------------------
// Kernel 2: per-chunk KV outer-product sums. 128 thr, 2 d-rows per thread.
// ---------------------------------------------------------------------------
__global__ __launch_bounds__(128) void chunk_kv_kernel()
{
    const int b = blockIdx.x;
    const int c = b & (N_CHUNK - 1);
    const int h = (b >> 6) & (N_H - 1);
    const int n = b >> 10;

    __shared__ float Ks[CHUNK][D_H];
    __shared__ float Vs[CHUNK][D_H];

    const int tid = threadIdx.x;
    const int tx  = tid & 7;
    const int ty  = tid >> 3;          // 0..15
    const int e0  = tx * 4;

    #pragma unroll
    for (int rr = 0; rr < 2; rr++) {
        int l = ty + rr * 16;
        size_t base = (size_t)(n * L_SEQ + c * CHUNK + l) * DIM + h * D_H + e0;
        *reinterpret_cast<float4*>(&Ks[l][e0]) = *reinterpret_cast<const float4*>(&g_K[base]);
        *reinterpret_cast<float4*>(&Vs[l][e0]) = *reinterpret_cast<const float4*>(&g_V[base]);
    }
    __syncthreads();

    float a0[4] = {}, a1[4] = {};
    #pragma unroll
    for (int l = 0; l < CHUNK; l++) {
        float k0 = Ks[l][ty];
        float k1 = Ks[l][ty + 16];
        float4 v4 = *reinterpret_cast<const float4*>(&Vs[l][e0]);
        a0[0] = fmaf(k0, v4.x, a0[0]); a0[1] = fmaf(k0, v4.y, a0[1]);
        a0[2] = fmaf(k0, v4.z, a0[2]); a0[3] = fmaf(k0, v4.w, a0[3]);
        a1[0] = fmaf(k1, v4.x, a1[0]); a1[1] = fmaf(k1, v4.y, a1[1]);
        a1[2] = fmaf(k1, v4.z, a1[2]); a1[3] = fmaf(k1, v4.w, a1[3]);
    }
    size_t sp = ((size_t)((n * N_H + h) * N_CHUNK + c) * D_H + ty) * D_H + e0;
    *reinterpret_cast<float4*>(&g_S[sp]) = make_float4(a0[0], a0[1], a0[2], a0[3]);
    *reinterpret_cast<float4*>(&g_S[sp + 16 * D_H]) = make_float4(a1[0], a1[1], a1[2], a1[3]);
}

// ---------------------------------------------------------------------------
// Kernel 3: exclusive prefix-scan over chunks, 8-wide batched loads for MLP.
// ---------------------------------------------------------------------------
__global__ __launch_bounds__(256) void scan_kernel()
{
    const int lane = blockIdx.x * blockDim.x + threadIdx.x;
    const int idx = lane & (D_H * D_H - 1);
    const int nh  = lane >> 10;
    float* base = &g_S[(size_t)nh * N_CHUNK * D_H * D_H + idx];
    float run = 0.f;
    #pragma unroll
    for (int b = 0; b < 8; b++) {
        float v[8];
        #pragma unroll
        for (int j = 0; j < 8; j++)
            v[j] = base[(size_t)(b * 8 + j) * (D_H * D_H)];
        #pragma unroll
        for (int j = 0; j < 8; j++) {
            base[(size_t)(b * 8 + j) * (D_H * D_H)] = run;
            run += v[j];
        }
    }
}

// ---------------------------------------------------------------------------
// Kernel 4: per-chunk output. 128 thr, 2 rows per thread; d-major K.
// ---------------------------------------------------------------------------
__global__ __launch_bounds__(128) void out_kernel(float* __restrict__ out)
{
    const int b = blockIdx.x;
    const int c = b & (N_CHUNK - 1);
    const int h = (b >> 6) & (N_H - 1);
    const int n = b >> 10;

    __shared__ float Qs[CHUNK][33];
    __shared__ float Kt[D_H][36];
    __shared__ float Vs[CHUNK][D_H];
    __shared__ float Sp[D_H][D_H];
    __shared__ float Am[CHUNK][33];

    const int tid = threadIdx.x;
    const int tx  = tid & 7;
    const int ty  = tid >> 3;          // 0..15
    const int j0  = tx * 4;

    #pragma unroll
    for (int rr = 0; rr < 2; rr++) {
        int l = ty + rr * 16;
        size_t base = (size_t)(n * L_SEQ + c * CHUNK + l) * DIM + h * D_H + j0;
        float4 q4 = *reinterpret_cast<const float4*>(&g_Q[base]);
        Qs[l][j0 + 0] = q4.x; Qs[l][j0 + 1] = q4.y; Qs[l][j0 + 2] = q4.z; Qs[l][j0 + 3] = q4.w;
        float4 k4 = *reinterpret_cast<const float4*>(&g_K[base]);
        Kt[j0 + 0][l] = k4.x; Kt[j0 + 1][l] = k4.y; Kt[j0 + 2][l] = k4.z; Kt[j0 + 3][l] = k4.w;
        *reinterpret_cast<float4*>(&Vs[l][j0]) = *reinterpret_cast<const float4*>(&g_V[base]);
        size_t sb2 = (size_t)((n * N_H + h) * N_CHUNK + c) * D_H * D_H + l * D_H + j0;
        *reinterpret_cast<float4*>(&Sp[l][j0]) = *reinterpret_cast<const float4*>(&g_S[sb2]);
    }
    __syncthreads();

    const int r0 = ty, r1 = ty + 16;

    // A[r][j0..3] = Q_r . K_j for r in {r0, r1}
    float a0[4] = {}, a1[4] = {};
    #pragma unroll
    for (int d = 0; d < D_H; d++) {
        float q0 = Qs[r0][d];
        float q1 = Qs[r1][d];
        float4 k4 = *reinterpret_cast<const float4*>(&Kt[d][j0]);
        a0[0] = fmaf(q0, k4.x, a0[0]); a0[1] = fmaf(q0, k4.y, a0[1]);
        a0[2] = fmaf(q0, k4.z, a0[2]); a0[3] = fmaf(q0, k4.w, a0[3]);
        a1[0] = fmaf(q1, k4.x, a1[0]); a1[1] = fmaf(q1, k4.y, a1[1]);
        a1[2] = fmaf(q1, k4.z, a1[2]); a1[3] = fmaf(q1, k4.w, a1[3]);
    }
    #pragma unroll
    for (int jj = 0; jj < 4; jj++) {
        Am[r0][j0 + jj] = (j0 + jj <= r0) ? a0[jj] : 0.f;
        Am[r1][j0 + jj] = (j0 + jj <= r1) ? a1[jj] : 0.f;
    }
    __syncthreads();

    const int e0 = j0;
    float o0[4] = {}, o1[4] = {};
    #pragma unroll
    for (int d = 0; d < D_H; d++) {
        float q0 = Qs[r0][d];
        float q1 = Qs[r1][d];
        float4 s4 = *reinterpret_cast<const float4*>(&Sp[d][e0]);
        o0[0] = fmaf(q0, s4.x, o0[0]); o0[1] = fmaf(q0, s4.y, o0[1]);
        o0[2] = fmaf(q0, s4.z, o0[2]); o0[3] = fmaf(q0, s4.w, o0[3]);
        o1[0] = fmaf(q1, s4.x, o1[0]); o1[1] = fmaf(q1, s4.y, o1[1]);
        o1[2] = fmaf(q1, s4.z, o1[2]); o1[3] = fmaf(q1, s4.w, o1[3]);
    }
    #pragma unroll
    for (int j = 0; j < CHUNK; j++) {
        float m0 = Am[r0][j];
        float m1 = Am[r1][j];
        float4 v4 = *reinterpret_cast<const float4*>(&Vs[j][e0]);
        o0[0] = fmaf(m0, v4.x, o0[0]); o0[1] = fmaf(m0, v4.y, o0[1]);
        o0[2] = fmaf(m0, v4.z, o0[2]); o0[3] = fmaf(m0, v4.w, o0[3]);
        o1[0] = fmaf(m1, v4.x, o1[0]); o1[1] = fmaf(m1, v4.y, o1[1]);
        o1[2] = fmaf(m1, v4.z, o1[2]); o1[3] = fmaf(m1, v4.w, o1[3]);
    }
    size_t ob0 = (size_t)(n * L_SEQ + c * CHUNK + r0) * DIM + h * D_H + e0;
    size_t ob1 = (size_t)(n * L_SEQ + c * CHUNK + r1) * DIM + h * D_H + e0;
    *reinterpret_cast<float4*>(&out[ob0]) = make_float4(o0[0], o0[1], o0[2], o0[3]);
    *reinterpret_cast<float4*>(&out[ob1]) = make_float4(o1[0], o1[1], o1[2], o1[3]);
}

// ---------------------------------------------------------------------------
extern "C" void kernel_launch(void* const* d_in, const int* in_sizes, int n_in,
                              void* d_out, int out_size)
{
    const float* query = (const float*)d_in[0];
    const float* key   = (const float*)d_in[1];
    const float* Wq    = (const float*)d_in[2];
    const float* Wk    = (const float*)d_in[3];
    const float* Wv    = (const float*)d_in[4];
    float* out = (float*)d_out;

    cudaFuncSetAttribute(proj_mma_kernel,
                         cudaFuncAttributeMaxDynamicSharedMemorySize, SMEM_BYTES);

    int conv_blocks = (2 * NQ4 + 3 * NW4) / 256;
    convert_kernel<<<conv_blocks, 256>>>(query, key, Wq, Wk, Wv);

    dim3 gp(DIM / 128, TOT_ROWS / 128, 3);      // (4, 64, 3) = 768 CTAs
    proj_mma_kernel<<<gp, 256, SMEM_BYTES>>>();

    chunk_kv_kernel<<<N_B * N_H * N_CHUNK, 128>>>();
    scan_kernel<<<(N_B * N_H * D_H * D_H) / 256, 256>>>();
    out_kernel<<<N_B * N_H * N_CHUNK, 128>>>(out);
}

// round 7
// speedup vs baseline: 4.0228x; 1.2724x over previous
#include <cuda_runtime.h>
#include <cuda_fp16.h>
#include <cstdint>

#define N_B   4
#define L_SEQ 2048
#define N_H   16
#define D_H   32
#define DIM   512
#define CHUNK 32
#define N_CHUNK (L_SEQ / CHUNK)     // 64
#define TOT_ROWS (N_B * L_SEQ)      // 8192

// ---------------- device scratch (allocation-free rule) ----------------
__device__ float g_Q[TOT_ROWS * DIM];
__device__ float g_K[TOT_ROWS * DIM];
__device__ float g_V[TOT_ROWS * DIM];
__device__ float g_S[N_B * N_H * N_CHUNK * D_H * D_H];

// fp16 operands (single precision level; activation fp16 error dominates anyway)
__device__ __half hQ[TOT_ROWS * DIM];
__device__ __half hK[TOT_ROWS * DIM];
__device__ __half hW[3][DIM * DIM];

// ---------------- helpers ----------------
__device__ __forceinline__ uint32_t smem_u32(const void* p) {
    uint32_t a;
    asm("{ .reg .u64 t; cvta.to.shared.u64 t, %1; cvt.u32.u64 %0, t; }" : "=r"(a) : "l"(p));
    return a;
}
__device__ __forceinline__ void cp16(uint32_t dst, const void* src) {
    asm volatile("cp.async.cg.shared.global [%0], [%1], 16;" :: "r"(dst), "l"(src));
}
__device__ __forceinline__ void cp_commit() { asm volatile("cp.async.commit_group;" ::: "memory"); }
template<int N> __device__ __forceinline__ void cp_wait() {
    asm volatile("cp.async.wait_group %0;" :: "n"(N) : "memory");
}
__device__ __forceinline__ void ldsm4(uint32_t* r, uint32_t a) {
    asm volatile("ldmatrix.sync.aligned.m8n8.x4.shared.b16 {%0,%1,%2,%3}, [%4];"
                 : "=r"(r[0]), "=r"(r[1]), "=r"(r[2]), "=r"(r[3]) : "r"(a));
}
__device__ __forceinline__ void mma16816(float* d, const uint32_t* a, uint32_t b0, uint32_t b1) {
    asm volatile(
        "mma.sync.aligned.m16n8k16.row.col.f32.f16.f16.f32 "
        "{%0,%1,%2,%3}, {%4,%5,%6,%7}, {%8,%9}, {%0,%1,%2,%3};"
        : "+f"(d[0]), "+f"(d[1]), "+f"(d[2]), "+f"(d[3])
        : "r"(a[0]), "r"(a[1]), "r"(a[2]), "r"(a[3]), "r"(b0), "r"(b1));
}

// ---------------------------------------------------------------------------
// Kernel 0: fp32 -> fp16
// ---------------------------------------------------------------------------
#define NQ4 (TOT_ROWS * DIM / 4)
#define NW4 (DIM * DIM / 4)

__global__ __launch_bounds__(256) void convert_kernel(
    const float* __restrict__ q, const float* __restrict__ k,
    const float* __restrict__ wq, const float* __restrict__ wk,
    const float* __restrict__ wv)
{
    int idx = blockIdx.x * 256 + threadIdx.x;
    const float* src;
    __half* dst;
    int rel;
    if (idx < NQ4)          { src = q;  dst = hQ;    rel = idx; }
    else if (idx < 2 * NQ4) { src = k;  dst = hK;    rel = idx - NQ4; }
    else {
        int t = idx - 2 * NQ4;
        int w = t / NW4;
        rel = t - w * NW4;
        src = (w == 0) ? wq : (w == 1 ? wk : wv);
        dst = hW[w];
    }
    float4 v = reinterpret_cast<const float4*>(src)[rel];
    reinterpret_cast<__half2*>(dst)[rel * 2] =
        make_half2(__float2half_rn(v.x), __float2half_rn(v.y));
    reinterpret_cast<__half2*>(dst)[rel * 2 + 1] =
        make_half2(__float2half_rn(v.z), __float2half_rn(v.w));
}

// ---------------------------------------------------------------------------
// Kernel 1: HMMA projection GEMM (fp16 single pass).
// CTA 128x128, 8 warps of 64x32, BK=64, 3-stage cp.async pipeline, 2 CTA/SM.
// ---------------------------------------------------------------------------
#define SR 72                         // smem row stride in halfwords (144B)
#define TILE_HW (128 * SR)
#define TILE_B  (TILE_HW * 2)         // 18432 B
#define SMEM_BYTES (6 * TILE_B)       // A x3, B x3 = 110592

__global__ __launch_bounds__(256, 2) void proj_mma_kernel()
{
    extern __shared__ char smem_raw[];
    const uint32_t sb = smem_u32(smem_raw);
    const int tid  = threadIdx.x;
    const int wid  = tid >> 5;
    const int lane = tid & 31;
    const int warp_m = wid & 1;
    const int warp_n = wid >> 1;

    const int z  = blockIdx.z;
    const int bm = blockIdx.y * 128;
    const int bn = blockIdx.x * 128;
    const __half* A = (z == 0) ? hQ : hK;
    const __half* B = hW[z];
    float* O = (z == 0) ? g_Q : (z == 1 ? g_K : g_V);

    auto tA = [&](int buf) { return sb + (uint32_t)buf * TILE_B; };
    auto tB = [&](int buf) { return sb + (uint32_t)(3 + buf) * TILE_B; };

    // load one BK=64 chunk (128 rows x 64 halfs = 8 x 16B segs per row)
    auto prefetch = [&](int c, int buf) {
        const int k0 = c * 64;
        #pragma unroll
        for (int i = 0; i < 4; i++) {
            int idx = tid + 256 * i;
            int row = idx >> 3, seg = idx & 7;
            uint32_t doff = (uint32_t)(row * SR + seg * 8) * 2;
            cp16(tA(buf) + doff, A + (size_t)(bm + row) * DIM + k0 + seg * 8);
            cp16(tB(buf) + doff, B + (size_t)(bn + row) * DIM + k0 + seg * 8);
        }
        cp_commit();
    };

    float acc[4][4][4] = {};
    prefetch(0, 0);
    prefetch(1, 1);

    const int jA = lane >> 3;
    const int rA = lane & 7;

    for (int c = 0; c < 8; c++) {
        const int buf = c % 3;
        if (c + 2 < 8) {
            prefetch(c + 2, (c + 2) % 3);
            cp_wait<2>();
        } else if (c + 1 < 8) {
            cp_wait<1>();
        } else {
            cp_wait<0>();
        }
        __syncthreads();

        #pragma unroll
        for (int ks = 0; ks < 4; ks++) {
            uint32_t fA[4][4], fB[2][4];
            #pragma unroll
            for (int mt = 0; mt < 4; mt++) {
                uint32_t off = (uint32_t)((warp_m * 64 + mt * 16 + (jA & 1) * 8 + rA) * SR
                                          + ks * 16 + (jA >> 1) * 8) * 2;
                ldsm4(fA[mt], tA(buf) + off);
            }
            #pragma unroll
            for (int g = 0; g < 2; g++) {
                uint32_t off = (uint32_t)((warp_n * 32 + g * 16 + (jA & 1) * 8 + rA) * SR
                                          + ks * 16 + (jA >> 1) * 8) * 2;
                ldsm4(fB[g], tB(buf) + off);
            }
            #pragma unroll
            for (int mt = 0; mt < 4; mt++)
                #pragma unroll
                for (int nt = 0; nt < 4; nt++) {
                    int g = nt >> 1, s = nt & 1;
                    mma16816(acc[mt][nt], fA[mt], fB[g][s], fB[g][s + 2]);
                }
        }
        __syncthreads();   // all warps done with buf before it is re-filled
    }

    // Epilogue: per-row softmax over this warp's 32-col head (z<2), store fp32.
    const int qlane = lane & 3;
    #pragma unroll
    for (int mt = 0; mt < 4; mt++) {
        #pragma unroll
        for (int rh = 0; rh < 2; rh++) {
            float v[4][2];
            #pragma unroll
            for (int nt = 0; nt < 4; nt++) {
                v[nt][0] = acc[mt][nt][2 * rh + 0];
                v[nt][1] = acc[mt][nt][2 * rh + 1];
            }
            if (z < 2) {
                float mx = v[0][0];
                #pragma unroll
                for (int nt = 0; nt < 4; nt++) {
                    mx = fmaxf(mx, v[nt][0]);
                    mx = fmaxf(mx, v[nt][1]);
                }
                mx = fmaxf(mx, __shfl_xor_sync(0xffffffffu, mx, 1));
                mx = fmaxf(mx, __shfl_xor_sync(0xffffffffu, mx, 2));
                float s = 0.f;
                #pragma unroll
                for (int nt = 0; nt < 4; nt++) {
                    v[nt][0] = expf(v[nt][0] - mx);
                    v[nt][1] = expf(v[nt][1] - mx);
                    s += v[nt][0] + v[nt][1];
                }
                s += __shfl_xor_sync(0xffffffffu, s, 1);
                s += __shfl_xor_sync(0xffffffffu, s, 2);
                float inv = 1.f / s;
                #pragma unroll
                for (int nt = 0; nt < 4; nt++) { v[nt][0] *= inv; v[nt][1] *= inv; }
            }
            int row = bm + warp_m * 64 + mt * 16 + (lane >> 2) + rh * 8;
            #pragma unroll
            for (int nt = 0; nt < 4; nt++) {
                int col = bn + warp_n * 32 + nt * 8 + 2 * qlane;
                *reinterpret_cast<float2*>(&O[(size_t)row * DIM + col]) =
                    make_float2(v[nt][0], v[nt][1]);
            }
        }
    }
}

// ---------------------------------------------------------------------------
// Kernel 2: per-chunk KV outer-product sums. 128 thr, 2 d-rows per thread.
// ---------------------------------------------------------------------------
__global__ __launch_bounds__(128) void chunk_kv_kernel()
{
    const int b = blockIdx.x;
    const int c = b & (N_CHUNK - 1);
    const int h = (b >> 6) & (N_H - 1);
    const int n = b >> 10;

    __shared__ float Ks[CHUNK][D_H];
    __shared__ float Vs[CHUNK][D_H];

    const int tid = threadIdx.x;
    const int tx  = tid & 7;
    const int ty  = tid >> 3;
    const int e0  = tx * 4;

    #pragma unroll
    for (int rr = 0; rr < 2; rr++) {
        int l = ty + rr * 16;
        size_t base = (size_t)(n * L_SEQ + c * CHUNK + l) * DIM + h * D_H + e0;
        *reinterpret_cast<float4*>(&Ks[l][e0]) = *reinterpret_cast<const float4*>(&g_K[base]);
        *reinterpret_cast<float4*>(&Vs[l][e0]) = *reinterpret_cast<const float4*>(&g_V[base]);
    }
    __syncthreads();

    float a0[4] = {}, a1[4] = {};
    #pragma unroll
    for (int l = 0; l < CHUNK; l++) {
        float k0 = Ks[l][ty];
        float k1 = Ks[l][ty + 16];
        float4 v4 = *reinterpret_cast<const float4*>(&Vs[l][e0]);
        a0[0] = fmaf(k0, v4.x, a0[0]); a0[1] = fmaf(k0, v4.y, a0[1]);
        a0[2] = fmaf(k0, v4.z, a0[2]); a0[3] = fmaf(k0, v4.w, a0[3]);
        a1[0] = fmaf(k1, v4.x, a1[0]); a1[1] = fmaf(k1, v4.y, a1[1]);
        a1[2] = fmaf(k1, v4.z, a1[2]); a1[3] = fmaf(k1, v4.w, a1[3]);
    }
    size_t sp = ((size_t)((n * N_H + h) * N_CHUNK + c) * D_H + ty) * D_H + e0;
    *reinterpret_cast<float4*>(&g_S[sp]) = make_float4(a0[0], a0[1], a0[2], a0[3]);
    *reinterpret_cast<float4*>(&g_S[sp + 16 * D_H]) = make_float4(a1[0], a1[1], a1[2], a1[3]);
}

// ---------------------------------------------------------------------------
// Kernel 3: exclusive prefix-scan over chunks, 8-wide batched loads for MLP.
// ---------------------------------------------------------------------------
__global__ __launch_bounds__(256) void scan_kernel()
{
    const int lane = blockIdx.x * blockDim.x + threadIdx.x;
    const int idx = lane & (D_H * D_H - 1);
    const int nh  = lane >> 10;
    float* base = &g_S[(size_t)nh * N_CHUNK * D_H * D_H + idx];
    float run = 0.f;
    #pragma unroll
    for (int b = 0; b < 8; b++) {
        float v[8];
        #pragma unroll
        for (int j = 0; j < 8; j++)
            v[j] = base[(size_t)(b * 8 + j) * (D_H * D_H)];
        #pragma unroll
        for (int j = 0; j < 8; j++) {
            base[(size_t)(b * 8 + j) * (D_H * D_H)] = run;
            run += v[j];
        }
    }
}

// ---------------------------------------------------------------------------
// Kernel 4: per-chunk output. 128 thr, 2 rows per thread; d-major K.
// ---------------------------------------------------------------------------
__global__ __launch_bounds__(128) void out_kernel(float* __restrict__ out)
{
    const int b = blockIdx.x;
    const int c = b & (N_CHUNK - 1);
    const int h = (b >> 6) & (N_H - 1);
    const int n = b >> 10;

    __shared__ float Qs[CHUNK][33];
    __shared__ float Kt[D_H][36];
    __shared__ float Vs[CHUNK][D_H];
    __shared__ float Sp[D_H][D_H];
    __shared__ float Am[CHUNK][33];

    const int tid = threadIdx.x;
    const int tx  = tid & 7;
    const int ty  = tid >> 3;
    const int j0  = tx * 4;

    #pragma unroll
    for (int rr = 0; rr < 2; rr++) {
        int l = ty + rr * 16;
        size_t base = (size_t)(n * L_SEQ + c * CHUNK + l) * DIM + h * D_H + j0;
        float4 q4 = *reinterpret_cast<const float4*>(&g_Q[base]);
        Qs[l][j0 + 0] = q4.x; Qs[l][j0 + 1] = q4.y; Qs[l][j0 + 2] = q4.z; Qs[l][j0 + 3] = q4.w;
        float4 k4 = *reinterpret_cast<const float4*>(&g_K[base]);
        Kt[j0 + 0][l] = k4.x; Kt[j0 + 1][l] = k4.y; Kt[j0 + 2][l] = k4.z; Kt[j0 + 3][l] = k4.w;
        *reinterpret_cast<float4*>(&Vs[l][j0]) = *reinterpret_cast<const float4*>(&g_V[base]);
        size_t sb2 = (size_t)((n * N_H + h) * N_CHUNK + c) * D_H * D_H + l * D_H + j0;
        *reinterpret_cast<float4*>(&Sp[l][j0]) = *reinterpret_cast<const float4*>(&g_S[sb2]);
    }
    __syncthreads();

    const int r0 = ty, r1 = ty + 16;

    float a0[4] = {}, a1[4] = {};
    #pragma unroll
    for (int d = 0; d < D_H; d++) {
        float q0 = Qs[r0][d];
        float q1 = Qs[r1][d];
        float4 k4 = *reinterpret_cast<const float4*>(&Kt[d][j0]);
        a0[0] = fmaf(q0, k4.x, a0[0]); a0[1] = fmaf(q0, k4.y, a0[1]);
        a0[2] = fmaf(q0, k4.z, a0[2]); a0[3] = fmaf(q0, k4.w, a0[3]);
        a1[0] = fmaf(q1, k4.x, a1[0]); a1[1] = fmaf(q1, k4.y, a1[1]);
        a1[2] = fmaf(q1, k4.z, a1[2]); a1[3] = fmaf(q1, k4.w, a1[3]);
    }
    #pragma unroll
    for (int jj = 0; jj < 4; jj++) {
        Am[r0][j0 + jj] = (j0 + jj <= r0) ? a0[jj] : 0.f;
        Am[r1][j0 + jj] = (j0 + jj <= r1) ? a1[jj] : 0.f;
    }
    __syncthreads();

    const int e0 = j0;
    float o0[4] = {}, o1[4] = {};
    #pragma unroll
    for (int d = 0; d < D_H; d++) {
        float q0 = Qs[r0][d];
        float q1 = Qs[r1][d];
        float4 s4 = *reinterpret_cast<const float4*>(&Sp[d][e0]);
        o0[0] = fmaf(q0, s4.x, o0[0]); o0[1] = fmaf(q0, s4.y, o0[1]);
        o0[2] = fmaf(q0, s4.z, o0[2]); o0[3] = fmaf(q0, s4.w, o0[3]);
        o1[0] = fmaf(q1, s4.x, o1[0]); o1[1] = fmaf(q1, s4.y, o1[1]);
        o1[2] = fmaf(q1, s4.z, o1[2]); o1[3] = fmaf(q1, s4.w, o1[3]);
    }
    #pragma unroll
    for (int j = 0; j < CHUNK; j++) {
        float m0 = Am[r0][j];
        float m1 = Am[r1][j];
        float4 v4 = *reinterpret_cast<const float4*>(&Vs[j][e0]);
        o0[0] = fmaf(m0, v4.x, o0[0]); o0[1] = fmaf(m0, v4.y, o0[1]);
        o0[2] = fmaf(m0, v4.z, o0[2]); o0[3] = fmaf(m0, v4.w, o0[3]);
        o1[0] = fmaf(m1, v4.x, o1[0]); o1[1] = fmaf(m1, v4.y, o1[1]);
        o1[2] = fmaf(m1, v4.z, o1[2]); o1[3] = fmaf(m1, v4.w, o1[3]);
    }
    size_t ob0 = (size_t)(n * L_SEQ + c * CHUNK + r0) * DIM + h * D_H + e0;
    size_t ob1 = (size_t)(n * L_SEQ + c * CHUNK + r1) * DIM + h * D_H + e0;
    *reinterpret_cast<float4*>(&out[ob0]) = make_float4(o0[0], o0[1], o0[2], o0[3]);
    *reinterpret_cast<float4*>(&out[ob1]) = make_float4(o1[0], o1[1], o1[2], o1[3]);
}

// ---------------------------------------------------------------------------
extern "C" void kernel_launch(void* const* d_in, const int* in_sizes, int n_in,
                              void* d_out, int out_size)
{
    const float* query = (const float*)d_in[0];
    const float* key   = (const float*)d_in[1];
    const float* Wq    = (const float*)d_in[2];
    const float* Wk    = (const float*)d_in[3];
    const float* Wv    = (const float*)d_in[4];
    float* out = (float*)d_out;

    cudaFuncSetAttribute(proj_mma_kernel,
                         cudaFuncAttributeMaxDynamicSharedMemorySize, SMEM_BYTES);

    int conv_blocks = (2 * NQ4 + 3 * NW4) / 256;
    convert_kernel<<<conv_blocks, 256>>>(query, key, Wq, Wk, Wv);

    dim3 gp(DIM / 128, TOT_ROWS / 128, 3);      // (4, 64, 3) = 768 CTAs
    proj_mma_kernel<<<gp, 256, SMEM_BYTES>>>();

    chunk_kv_kernel<<<N_B * N_H * N_CHUNK, 128>>>();
    scan_kernel<<<(N_B * N_H * D_H * D_H) / 256, 256>>>();
    out_kernel<<<N_B * N_H * N_CHUNK, 128>>>(out);
}